// round 1
// baseline (speedup 1.0000x reference)
#include <cuda_runtime.h>
#include <math.h>

#define BB  8
#define MM  36
#define DD  512
#define HWW 196
#define TT  64
#define NN  7056          // MM*HWW
#define PP  64            // BB*BB pairs
#define G1  4.0f
#define G2  5.0f

// ---------------- scratch (device globals; no allocation) ----------------
__device__ float d_V[BB * NN * DD];        // (B, N, D) region features, 115.6 MB
__device__ float d_W4[PP * TT * NN];       // exp(4*norm_sim) per pair, 115.6 MB
__device__ float d_G[PP * TT * DD];        // unnormalized v_tidal, 8.4 MB
__device__ float d_normsq[BB * NN];        // per-region squared norms
__device__ float d_u[BB * MM * DD];        // sum of normalized rows per box
__device__ float d_Zt[PP * TT];            // attn denominators
__device__ float d_sExp[PP * TT * MM];     // per-box sums of exp(norm_sim)
__device__ float d_S[PP];                  // pair scores
__device__ float d_betas[BB * TT * MM];    // diagonal betas

// ---------------- kernel 0: zero accumulators ----------------
__global__ void k_init() {
    int idx = blockIdx.x * blockDim.x + threadIdx.x;
    if (idx < BB * NN)      d_normsq[idx] = 0.f;
    if (idx < PP * TT)      d_Zt[idx]     = 0.f;
    if (idx < PP * TT * MM) d_sExp[idx]   = 0.f;
}

// ---------------- kernel 1: transpose image -> V, accumulate norms ----------------
// image: (B, M, D, H, W).  V[b, m*196 + w*14 + h, d] = image[b,m,d,h,w]
__global__ void __launch_bounds__(256) k_transpose(const float* __restrict__ image) {
    __shared__ float tile[32 * 197];
    const int b = blockIdx.z, m = blockIdx.y, d0 = blockIdx.x * 32;
    const float* src = image + ((size_t)(b * MM + m) * DD + d0) * HWW;
    for (int idx = threadIdx.x; idx < 32 * HWW; idx += 256) {
        int dd = idx / HWW, hw = idx % HWW;
        tile[dd * 197 + hw] = src[idx];
    }
    __syncthreads();
    float* dst = d_V + (size_t)(b * NN + m * HWW) * DD + d0;
    for (int idx = threadIdx.x; idx < HWW * 32; idx += 256) {
        int nl = idx >> 5, dd = idx & 31;
        int w = nl / 14, h = nl % 14;                 // nl = w*14 + h
        dst[(size_t)nl * DD + dd] = tile[dd * 197 + h * 14 + w];
    }
    if (threadIdx.x < HWW) {
        int nl = threadIdx.x;
        int w = nl / 14, h = nl % 14;
        float s = 0.f;
        #pragma unroll
        for (int dd = 0; dd < 32; dd++) {
            float v = tile[dd * 197 + h * 14 + w];
            s = fmaf(v, v, s);
        }
        atomicAdd(&d_normsq[b * NN + m * HWW + nl], s);
    }
}

// ---------------- kernel 2: u[b,m,d] = sum_hw V / ||V_row|| ----------------
__global__ void __launch_bounds__(256) k_u() {
    const int m = blockIdx.x, b = blockIdx.y;
    __shared__ float inv[HWW];
    if (threadIdx.x < HWW)
        inv[threadIdx.x] = rsqrtf(d_normsq[b * NN + m * HWW + threadIdx.x]);
    __syncthreads();
    const float* vb = d_V + (size_t)(b * NN + m * HWW) * DD;
    for (int d = threadIdx.x; d < DD; d += 256) {
        float acc = 0.f;
        for (int hw = 0; hw < HWW; hw++)
            acc = fmaf(vb[(size_t)hw * DD + d], inv[hw], acc);
        d_u[(size_t)(b * MM + m) * DD + d] = acc;
    }
}

// ---------------- kernel 3: sim GEMM + softmax over T + stats ----------------
// Per block: one pair p, one 128-column tile of n. C[64 t][128 n] register GEMM,
// then column softmax over t, write W4 = exp(norm_sim)^4, accumulate Zt & per-box sums.
__global__ void __launch_bounds__(256) k_sim(const float* __restrict__ text) {
    const int p = blockIdx.y;
    const int i = p >> 3, j = p & 7;
    const int n0 = blockIdx.x * 128;
    __shared__ float pool[64 * 129];          // GEMM tiles then the C tile
    __shared__ float Zt_s[TT];
    __shared__ float sE_s[TT * 2];
    float* As = pool;                         // [64][33] e tile
    float* Bs = pool + 64 * 33;               // [128][33] v tile

    if (threadIdx.x < TT)     Zt_s[threadIdx.x] = 0.f;
    if (threadIdx.x < TT * 2) sE_s[threadIdx.x] = 0.f;

    float acc[4][8];
    #pragma unroll
    for (int r = 0; r < 4; r++)
        #pragma unroll
        for (int c = 0; c < 8; c++) acc[r][c] = 0.f;

    const int ty = threadIdx.x >> 4, tx = threadIdx.x & 15;
    const float* E  = text + (size_t)j * TT * DD;
    const float* Vi = d_V + (size_t)i * NN * DD;

    for (int k0 = 0; k0 < DD; k0 += 32) {
        __syncthreads();
        #pragma unroll
        for (int r = 0; r < 8; r++) {
            int idx = threadIdx.x + r * 256;
            int t = idx >> 5, k = idx & 31;
            As[t * 33 + k] = E[(size_t)t * DD + k0 + k];
        }
        #pragma unroll
        for (int r = 0; r < 16; r++) {
            int idx = threadIdx.x + r * 256;
            int nl = idx >> 5, k = idx & 31;
            int n = n0 + nl;
            Bs[nl * 33 + k] = (n < NN) ? Vi[(size_t)n * DD + k0 + k] : 0.f;
        }
        __syncthreads();
        #pragma unroll
        for (int kk = 0; kk < 32; kk++) {
            float a[4], bv[8];
            #pragma unroll
            for (int r = 0; r < 4; r++) a[r] = As[(ty * 4 + r) * 33 + kk];
            #pragma unroll
            for (int c = 0; c < 8; c++) bv[c] = Bs[(tx + c * 16) * 33 + kk];
            #pragma unroll
            for (int r = 0; r < 4; r++)
                #pragma unroll
                for (int c = 0; c < 8; c++)
                    acc[r][c] = fmaf(a[r], bv[c], acc[r][c]);
        }
    }
    __syncthreads();
    float* Cs = pool;                         // [64][129]
    #pragma unroll
    for (int r = 0; r < 4; r++)
        #pragma unroll
        for (int c = 0; c < 8; c++)
            Cs[(ty * 4 + r) * 129 + tx + c * 16] = acc[r][c];
    __syncthreads();

    const int m_base = n0 / HWW;
    if (threadIdx.x < 128) {
        const int col = threadIdx.x;
        const int n = n0 + col;
        const bool valid = (n < NN);
        const int bm = valid ? (n / HWW - m_base) : 0;
        float mx = -1e30f;
        for (int t = 0; t < TT; t++) mx = fmaxf(mx, Cs[t * 129 + col]);
        float ssum = 0.f;
        for (int t = 0; t < TT; t++) {
            float e = __expf(Cs[t * 129 + col] - mx);
            ssum += e;
            Cs[t * 129 + col] = e;            // stash exp, column-private
        }
        const float inv_s = 1.0f / ssum;
        float* w4row = d_W4 + (size_t)p * TT * NN + n;
        for (int t = 0; t < TT; t++) {
            float ns = Cs[t * 129 + col] * inv_s;   // norm_sim in (0,1)
            float en = __expf(ns);
            float e4 = en * en; e4 *= e4;           // exp(4*ns)
            if (!valid) { en = 0.f; e4 = 0.f; }
            else w4row[(size_t)t * NN] = e4;
            float z  = e4;
            float s0 = (bm == 0) ? en : 0.f;
            float s1 = en - s0;
            #pragma unroll
            for (int off = 16; off; off >>= 1) {
                z  += __shfl_down_sync(0xffffffffu, z,  off);
                s0 += __shfl_down_sync(0xffffffffu, s0, off);
                s1 += __shfl_down_sync(0xffffffffu, s1, off);
            }
            if ((threadIdx.x & 31) == 0) {
                atomicAdd(&Zt_s[t], z);
                atomicAdd(&sE_s[t * 2 + 0], s0);
                atomicAdd(&sE_s[t * 2 + 1], s1);
            }
        }
    }
    __syncthreads();
    if (threadIdx.x < TT)
        atomicAdd(&d_Zt[p * TT + threadIdx.x], Zt_s[threadIdx.x]);
    if (threadIdx.x < TT * 2) {
        int t = threadIdx.x >> 1, bm = threadIdx.x & 1;
        int m = m_base + bm;
        float v = sE_s[threadIdx.x];
        if (m < MM && v != 0.f)
            atomicAdd(&d_sExp[(size_t)(p * TT + t) * MM + m], v);
    }
}

// ---------------- kernel 4: G[p,t,d] = sum_n W4[p,t,n] * V[i,n,d] ----------------
__global__ void __launch_bounds__(256) k_gmm() {
    const int p = blockIdx.y;
    const int i = p >> 3;
    const int d0 = blockIdx.x * 128;
    __shared__ float As[64 * 49];             // W4 [t][kk]
    __shared__ float Bs[48 * 129];            // V  [kk][d]
    float acc[4][8];
    #pragma unroll
    for (int r = 0; r < 4; r++)
        #pragma unroll
        for (int c = 0; c < 8; c++) acc[r][c] = 0.f;

    const int ty = threadIdx.x >> 4, tx = threadIdx.x & 15;
    const float* Wp = d_W4 + (size_t)p * TT * NN;
    const float* Vi = d_V + (size_t)i * NN * DD;

    for (int k0 = 0; k0 < NN; k0 += 48) {     // 147 chunks, exact
        __syncthreads();
        #pragma unroll
        for (int r = 0; r < 12; r++) {
            int idx = threadIdx.x + r * 256;
            int t = idx / 48, kk = idx % 48;
            As[t * 49 + kk] = Wp[(size_t)t * NN + k0 + kk];
        }
        #pragma unroll
        for (int r = 0; r < 24; r++) {
            int idx = threadIdx.x + r * 256;
            int kk = idx >> 7, dl = idx & 127;
            Bs[kk * 129 + dl] = Vi[(size_t)(k0 + kk) * DD + d0 + dl];
        }
        __syncthreads();
        #pragma unroll
        for (int kk = 0; kk < 48; kk++) {
            float a[4], bv[8];
            #pragma unroll
            for (int r = 0; r < 4; r++) a[r] = As[(ty * 4 + r) * 49 + kk];
            #pragma unroll
            for (int c = 0; c < 8; c++) bv[c] = Bs[kk * 129 + tx + c * 16];
            #pragma unroll
            for (int r = 0; r < 4; r++)
                #pragma unroll
                for (int c = 0; c < 8; c++)
                    acc[r][c] = fmaf(a[r], bv[c], acc[r][c]);
        }
    }
    float* Gp = d_G + (size_t)p * TT * DD + d0;
    #pragma unroll
    for (int r = 0; r < 4; r++)
        #pragma unroll
        for (int c = 0; c < 8; c++)
            Gp[(size_t)(ty * 4 + r) * DD + tx + c * 16] = acc[r][c];
}

// ---------------- kernel 5: per-pair score S[p] ----------------
__global__ void __launch_bounds__(256) k_score(const float* __restrict__ text) {
    const int p = blockIdx.x, i = p >> 3, j = p & 7;
    __shared__ float sbeta[TT * MM];          // 9216 B
    __shared__ float sls[MM];
    __shared__ float sdiag[TT];
    __shared__ float snrm[MM], sdot[MM];
    __shared__ float Es[TT * 128];            // 32 KB e-chunk
    const int tid = threadIdx.x, lane = tid & 31, warp = tid >> 5;
    const float* E = text + (size_t)j * TT * DD;

    for (int idx = tid; idx < TT * MM; idx += 256)
        sbeta[idx] = d_sExp[(size_t)p * TT * MM + idx];
    if (tid < MM) { snrm[tid] = 0.f; sdot[tid] = 0.f; }
    __syncthreads();
    if (tid < MM) {
        float s = 0.f;
        for (int t = 0; t < TT; t++) s += sbeta[t * MM + tid];
        sls[tid] = 1.0f / s;
    }
    __syncthreads();
    for (int idx = tid; idx < TT * MM; idx += 256) {
        float v = sbeta[idx] * sls[idx % MM];
        sbeta[idx] = v;
        if (i == j) d_betas[(size_t)i * TT * MM + idx] = v;
    }
    __syncthreads();

    // diag[t] = (G[t]·e[t]) / Zt
    for (int t = warp; t < TT; t += 8) {
        const float* Gr = d_G + ((size_t)p * TT + t) * DD;
        const float* Er = E + (size_t)t * DD;
        float s = 0.f;
        for (int d = lane; d < DD; d += 32) s = fmaf(Gr[d], Er[d], s);
        #pragma unroll
        for (int off = 16; off; off >>= 1) s += __shfl_down_sync(0xffffffffu, s, off);
        if (lane == 0) sdiag[t] = s / d_Zt[p * TT + t];
    }

    // e_prime norms & dot with u, chunked over d
    const float* U = d_u + (size_t)i * MM * DD;
    const int grp = tid >> 7;                  // 0 or 1
    const int dl = tid & 127;
    for (int d0 = 0; d0 < DD; d0 += 128) {
        __syncthreads();
        for (int idx = tid; idx < TT * 128; idx += 256) {
            int t = idx >> 7, dloc = idx & 127;
            Es[idx] = E[(size_t)t * DD + d0 + dloc];
        }
        __syncthreads();
        for (int m = grp; m < MM; m += 2) {
            float v = 0.f;
            #pragma unroll 16
            for (int t = 0; t < TT; t++)
                v = fmaf(sbeta[t * MM + m], Es[t * 128 + dl], v);
            float nr = v * v;
            float dt = v * U[(size_t)m * DD + d0 + dl];
            #pragma unroll
            for (int off = 16; off; off >>= 1) {
                nr += __shfl_down_sync(0xffffffffu, nr, off);
                dt += __shfl_down_sync(0xffffffffu, dt, off);
            }
            if (lane == 0) { atomicAdd(&snrm[m], nr); atomicAdd(&sdot[m], dt); }
        }
    }
    __syncthreads();
    if (tid == 0) {
        float se = 0.f;
        for (int t = 0; t < TT; t++) se += expf(G2 * sdiag[t]);
        float r_qd = (1.0f / G2) * logf(se);
        float sm = 0.f;
        for (int m = 0; m < MM; m++)
            sm += expf(sdot[m] / ((float)HWW * sqrtf(snrm[m])));
        d_S[p] = r_qd + (1.0f / G2) * logf(sm);
    }
}

// ---------------- kernel 6: final scalar ----------------
// reg loss via ||B^T B||_F^2 - sum_t ||beta_t||^4  (== sum_{t!=s} (BB^T)^2)
__global__ void __launch_bounds__(256) k_final(const int* __restrict__ spinds,
                                               float* __restrict__ out) {
    __shared__ float sb[TT * MM];
    __shared__ float red[8];
    __shared__ float regsum;
    const int tid = threadIdx.x, lane = tid & 31, warp = tid >> 5;
    if (tid == 0) regsum = 0.f;
    for (int b = 0; b < BB; b++) {
        __syncthreads();
        for (int idx = tid; idx < TT * MM; idx += 256)
            sb[idx] = d_betas[(size_t)b * TT * MM + idx];
        __syncthreads();
        float lsum = 0.f;
        for (int idx = tid; idx < MM * MM; idx += 256) {
            int a = idx / MM, c = idx % MM;
            float v = 0.f;
            for (int t = 0; t < TT; t++)
                v = fmaf(sb[t * MM + a], sb[t * MM + c], v);
            lsum = fmaf(v, v, lsum);
        }
        for (int t = tid; t < TT; t += 256) {
            float v = 0.f;
            for (int m = 0; m < MM; m++)
                v = fmaf(sb[t * MM + m], sb[t * MM + m], v);
            lsum -= v * v;
        }
        #pragma unroll
        for (int off = 16; off; off >>= 1)
            lsum += __shfl_down_sync(0xffffffffu, lsum, off);
        if (lane == 0) red[warp] = lsum;
        __syncthreads();
        if (tid == 0) {
            float s = 0.f;
            for (int w = 0; w < 8; w++) s += red[w];
            regsum += sqrtf(fmaxf(s, 0.f));
        }
    }
    __syncthreads();
    if (tid == 0) {
        float l1 = 0.f, l2 = 0.f;
        for (int a = 0; a < BB; a++) {
            float num = expf(d_S[a * BB + a]);       // gamma3 cancels in the ratio
            float pdq = 0.f, pqd = 0.f;
            for (int k = 0; k < 5; k++) {
                int sp = spinds[a * 5 + k];
                pdq += expf(d_S[a * BB + sp]);
                pqd += expf(d_S[sp * BB + a]);
            }
            l1 += num / pdq;
            l2 += num / pqd;
        }
        out[0] = -(l1 / BB) - (l2 / BB) + regsum / (float)(BB * TT * MM);
    }
}

// ---------------- launcher ----------------
extern "C" void kernel_launch(void* const* d_in, const int* in_sizes, int n_in,
                              void* d_out, int out_size) {
    const float* image  = (const float*)d_in[0];
    const float* text   = (const float*)d_in[1];
    const int*   spinds = (const int*)d_in[3];
    float* out = (float*)d_out;

    k_init<<<576, 256>>>();
    {
        dim3 g(16, MM, BB);
        k_transpose<<<g, 256>>>(image);
    }
    {
        dim3 g(MM, BB);
        k_u<<<g, 256>>>();
    }
    {
        dim3 g((NN + 127) / 128, PP);   // 56 x 64
        k_sim<<<g, 256>>>(text);
    }
    {
        dim3 g(DD / 128, PP);           // 4 x 64
        k_gmm<<<g, 256>>>();
    }
    k_score<<<PP, 256>>>(text);
    k_final<<<1, 256>>>(spinds, out);
}

// round 2
// speedup vs baseline: 1.1662x; 1.1662x over previous
#include <cuda_runtime.h>
#include <math.h>

#define BB  8
#define MM  36
#define DD  512
#define HWW 196
#define TT  64
#define NN  7056          // MM*HWW
#define PP  64            // BB*BB pairs
#define G1  4.0f
#define G2  5.0f

// ---------------- scratch (device globals; no allocation) ----------------
__device__ float d_V[BB * NN * DD];        // (B, N, D) region features
__device__ float d_W4[PP * TT * NN];       // exp(4*norm_sim) per pair
__device__ float d_G[PP * TT * DD];        // unnormalized v_tidal (atomic accum)
__device__ float d_normsq[BB * NN];        // per-region squared norms
__device__ float d_u[BB * MM * DD];        // sum of normalized rows per box
__device__ float d_Zt[PP * TT];            // attn denominators
__device__ float d_sExp[PP * TT * MM];     // per-box sums of exp(norm_sim)
__device__ float d_S[PP];                  // pair scores
__device__ float d_betas[BB * TT * MM];    // diagonal betas

// ---------------- packed f32x2 helpers ----------------
__device__ __forceinline__ unsigned long long pack2(float a) {
    unsigned long long r;
    asm("mov.b64 %0, {%1, %1};" : "=l"(r) : "r"(__float_as_uint(a)));
    return r;
}
__device__ __forceinline__ void unpack2(unsigned long long v, float& lo, float& hi) {
    unsigned int l, h;
    asm("mov.b64 {%0, %1}, %2;" : "=r"(l), "=r"(h) : "l"(v));
    lo = __uint_as_float(l);
    hi = __uint_as_float(h);
}
__device__ __forceinline__ void fma2(unsigned long long& d,
                                     unsigned long long a, unsigned long long b) {
    asm("fma.rn.f32x2 %0, %1, %2, %0;" : "+l"(d) : "l"(a), "l"(b));
}

// ---------------- kernel 0: zero accumulators ----------------
__global__ void k_init() {
    int idx = blockIdx.x * blockDim.x + threadIdx.x;
    if (idx < BB * NN)       d_normsq[idx] = 0.f;
    if (idx < PP * TT)       d_Zt[idx]     = 0.f;
    if (idx < PP * TT * MM)  d_sExp[idx]   = 0.f;
    if (idx < PP * TT * DD)  d_G[idx]      = 0.f;
}

// ---------------- kernel 1: transpose image -> V, accumulate norms ----------------
__global__ void __launch_bounds__(256) k_transpose(const float* __restrict__ image) {
    __shared__ float tile[32 * 197];
    const int b = blockIdx.z, m = blockIdx.y, d0 = blockIdx.x * 32;
    const float* src = image + ((size_t)(b * MM + m) * DD + d0) * HWW;
    for (int idx = threadIdx.x; idx < 32 * HWW; idx += 256) {
        int dd = idx / HWW, hw = idx % HWW;
        tile[dd * 197 + hw] = src[idx];
    }
    __syncthreads();
    float* dst = d_V + (size_t)(b * NN + m * HWW) * DD + d0;
    for (int idx = threadIdx.x; idx < HWW * 32; idx += 256) {
        int nl = idx >> 5, dd = idx & 31;
        int w = nl / 14, h = nl % 14;                 // nl = w*14 + h
        dst[(size_t)nl * DD + dd] = tile[dd * 197 + h * 14 + w];
    }
    if (threadIdx.x < HWW) {
        int nl = threadIdx.x;
        int w = nl / 14, h = nl % 14;
        float s = 0.f;
        #pragma unroll
        for (int dd = 0; dd < 32; dd++) {
            float v = tile[dd * 197 + h * 14 + w];
            s = fmaf(v, v, s);
        }
        atomicAdd(&d_normsq[b * NN + m * HWW + nl], s);
    }
}

// ---------------- kernel 2: u[b,m,d] = sum_hw V / ||V_row|| ----------------
__global__ void __launch_bounds__(256) k_u() {
    const int m = blockIdx.x, b = blockIdx.y;
    __shared__ float inv[HWW];
    if (threadIdx.x < HWW)
        inv[threadIdx.x] = rsqrtf(d_normsq[b * NN + m * HWW + threadIdx.x]);
    __syncthreads();
    const float* vb = d_V + (size_t)(b * NN + m * HWW) * DD;
    for (int d = threadIdx.x; d < DD; d += 256) {
        float acc = 0.f;
        for (int hw = 0; hw < HWW; hw++)
            acc = fmaf(vb[(size_t)hw * DD + d], inv[hw], acc);
        d_u[(size_t)(b * MM + m) * DD + d] = acc;
    }
}

// ---------------- kernel 3: sim GEMM (packed f32x2) + softmax over T + stats ----
// Block: one pair p, 256-column tile of n. 64x256 tile, 8x8 per thread.
// C[t][n] = sum_k E[t][k] * V[n][k]
__global__ void __launch_bounds__(256) k_sim(const float* __restrict__ text) {
    const int p = blockIdx.y;
    const int i = p >> 3, j = p & 7;
    const int n0 = blockIdx.x * 256;

    __shared__ float sm[64 * 130];        // GEMM tiles, later Cs staging
    __shared__ float psum[64 * 2 * 4];
    __shared__ int   colm[128];
    float* As = sm;                       // [16][64]  k-major
    float* Bs = sm + 16 * 64;             // [16][260] k-major

    unsigned long long acc[8][4];
    #pragma unroll
    for (int r = 0; r < 8; r++)
        #pragma unroll
        for (int c = 0; c < 4; c++) acc[r][c] = 0ull;

    const int tx = threadIdx.x & 31, ty = threadIdx.x >> 5;
    const float* E  = text + (size_t)j * TT * DD;
    const float* Vi = d_V + (size_t)i * NN * DD;
    const int tA_t = threadIdx.x & 63;
    const int tA_k = (threadIdx.x >> 6) * 4;

    for (int k0 = 0; k0 < DD; k0 += 16) {
        __syncthreads();
        // As: E[t][k0+k] -> As[k][t]
        {
            float4 av = *(const float4*)&E[(size_t)tA_t * DD + k0 + tA_k];
            As[(tA_k + 0) * 64 + tA_t] = av.x;
            As[(tA_k + 1) * 64 + tA_t] = av.y;
            As[(tA_k + 2) * 64 + tA_t] = av.z;
            As[(tA_k + 3) * 64 + tA_t] = av.w;
        }
        // Bs: V[n][k0+k] -> Bs[k][n]
        #pragma unroll
        for (int r = 0; r < 4; r++) {
            int id = threadIdx.x + r * 256;   // [0,1024)
            int n = id >> 2, kq = (id & 3) * 4;
            int gn = n0 + n;
            float4 bv = (gn < NN) ? *(const float4*)&Vi[(size_t)gn * DD + k0 + kq]
                                  : make_float4(0.f, 0.f, 0.f, 0.f);
            Bs[(kq + 0) * 260 + n] = bv.x;
            Bs[(kq + 1) * 260 + n] = bv.y;
            Bs[(kq + 2) * 260 + n] = bv.z;
            Bs[(kq + 3) * 260 + n] = bv.w;
        }
        __syncthreads();
        #pragma unroll
        for (int kk = 0; kk < 16; kk++) {
            float4 a0 = *(const float4*)&As[kk * 64 + ty * 8];
            float4 a1 = *(const float4*)&As[kk * 64 + ty * 8 + 4];
            unsigned long long a2[8];
            a2[0] = pack2(a0.x); a2[1] = pack2(a0.y);
            a2[2] = pack2(a0.z); a2[3] = pack2(a0.w);
            a2[4] = pack2(a1.x); a2[5] = pack2(a1.y);
            a2[6] = pack2(a1.z); a2[7] = pack2(a1.w);
            ulonglong2 B0 = *(const ulonglong2*)&Bs[kk * 260 + tx * 8];
            ulonglong2 B1 = *(const ulonglong2*)&Bs[kk * 260 + tx * 8 + 4];
            unsigned long long b2[4] = {B0.x, B0.y, B1.x, B1.y};
            #pragma unroll
            for (int r = 0; r < 8; r++)
                #pragma unroll
                for (int c = 0; c < 4; c++)
                    fma2(acc[r][c], a2[r], b2[c]);
        }
    }

    // ---------------- epilogue: two halves of 128 columns ----------------
    const int m_base = n0 / HWW;
    float* Cs = sm;                        // [64][130]
    for (int h = 0; h < 2; h++) {
        __syncthreads();
        if ((tx >> 4) == h) {
            int cx = (tx & 15) * 8;
            #pragma unroll
            for (int r = 0; r < 8; r++)
                #pragma unroll
                for (int c = 0; c < 4; c++) {
                    float lo, hi;
                    unpack2(acc[r][c], lo, hi);
                    Cs[(ty * 8 + r) * 130 + cx + c * 2]     = lo;
                    Cs[(ty * 8 + r) * 130 + cx + c * 2 + 1] = hi;
                }
        }
        __syncthreads();
        // column phase: softmax over t for each column
        if (threadIdx.x < 128) {
            const int col = threadIdx.x;
            const int n = n0 + h * 128 + col;
            const bool valid = (n < NN);
            colm[col] = valid ? (n / HWW - m_base) : -1;
            float mx = -1e30f;
            for (int t = 0; t < TT; t++) mx = fmaxf(mx, Cs[t * 130 + col]);
            float ssum = 0.f;
            for (int t = 0; t < TT; t++) {
                float e = __expf(Cs[t * 130 + col] - mx);
                ssum += e;
                Cs[t * 130 + col] = e;
            }
            const float inv_s = 1.0f / ssum;
            if (valid) {
                float* w4p = d_W4 + (size_t)p * TT * NN + n;
                for (int t = 0; t < TT; t++) {
                    float ns = Cs[t * 130 + col] * inv_s;  // norm_sim
                    float en = __expf(ns);
                    Cs[t * 130 + col] = en;
                    float e4 = en * en; e4 *= e4;          // exp(4*ns)
                    w4p[(size_t)t * NN] = e4;
                }
            } else {
                for (int t = 0; t < TT; t++) Cs[t * 130 + col] = 0.f;
            }
        }
        __syncthreads();
        // row phase: reduce over columns per t
        if (threadIdx.x < 128) {
            const int t = threadIdx.x >> 1, half = threadIdx.x & 1;
            float z = 0.f, s0 = 0.f, s1 = 0.f, s2 = 0.f;
            const int c0 = half * 64;
            for (int c = c0; c < c0 + 64; c++) {
                float en = Cs[t * 130 + c];
                float e4 = en * en; e4 *= e4;
                z += e4;
                int bm = colm[c];
                s0 += (bm == 0) ? en : 0.f;
                s1 += (bm == 1) ? en : 0.f;
                s2 += (bm == 2) ? en : 0.f;
            }
            float* pp = &psum[(t * 2 + half) * 4];
            pp[0] = z; pp[1] = s0; pp[2] = s1; pp[3] = s2;
        }
        __syncthreads();
        if (threadIdx.x < 64) {
            const int t = threadIdx.x;
            const float* p0 = &psum[(t * 2) * 4];
            const float* p1 = &psum[(t * 2 + 1) * 4];
            atomicAdd(&d_Zt[p * TT + t], p0[0] + p1[0]);
            #pragma unroll
            for (int bm = 0; bm < 3; bm++) {
                float s = p0[1 + bm] + p1[1 + bm];
                int m = m_base + bm;
                if (m < MM && s != 0.f)
                    atomicAdd(&d_sExp[(size_t)(p * TT + t) * MM + m], s);
            }
        }
    }
}

// ---------------- kernel 4: G[p,t,d] += sum_n W4[p,t,n] * V[i,n,d] ----------------
// Block: pair p, 256-d tile, 1/4 of the n range. 8x8 per thread, packed f32x2.
#define KC2 28
#define KSPLIT 4
#define KRANGE (NN / KSPLIT)   // 1764 = 63 * 28
__global__ void __launch_bounds__(256) k_gmm() {
    const int p = blockIdx.z;
    const int i = p >> 3;
    const int d0 = blockIdx.x * 256;
    const int kb0 = blockIdx.y * KRANGE;

    __shared__ float As[KC2 * 65];        // [28][65]  (W4, k-major, padded)
    __shared__ float Bs[KC2 * 260];       // [28][260] (V, k-major)

    unsigned long long acc[8][4];
    #pragma unroll
    for (int r = 0; r < 8; r++)
        #pragma unroll
        for (int c = 0; c < 4; c++) acc[r][c] = 0ull;

    const int tx = threadIdx.x & 31, ty = threadIdx.x >> 5;
    const float* Wp = d_W4 + (size_t)p * TT * NN;
    const float* Vi = d_V + (size_t)i * NN * DD;

    for (int kc = 0; kc < KRANGE / KC2; kc++) {
        const int kb = kb0 + kc * KC2;
        __syncthreads();
        // As: W4[t][kb+k] -> As[k][t]   (1792 elems, 7 per thread)
        #pragma unroll
        for (int r = 0; r < 7; r++) {
            int id = threadIdx.x + r * 256;
            int t = id / KC2, k = id % KC2;
            As[k * 65 + t] = Wp[(size_t)t * NN + kb + k];
        }
        // Bs: V[kb+k][d0+d]  (7168 floats = 1792 float4, 7 per thread)
        #pragma unroll
        for (int r = 0; r < 7; r++) {
            int id = threadIdx.x + r * 256;
            int k = id >> 6, dq = (id & 63) * 4;
            float4 bv = *(const float4*)&Vi[(size_t)(kb + k) * DD + d0 + dq];
            Bs[k * 260 + dq + 0] = bv.x;
            Bs[k * 260 + dq + 1] = bv.y;
            Bs[k * 260 + dq + 2] = bv.z;
            Bs[k * 260 + dq + 3] = bv.w;
        }
        __syncthreads();
        #pragma unroll
        for (int kk = 0; kk < KC2; kk++) {
            unsigned long long a2[8];
            #pragma unroll
            for (int r = 0; r < 8; r++)
                a2[r] = pack2(As[kk * 65 + ty * 8 + r]);
            ulonglong2 B0 = *(const ulonglong2*)&Bs[kk * 260 + tx * 8];
            ulonglong2 B1 = *(const ulonglong2*)&Bs[kk * 260 + tx * 8 + 4];
            unsigned long long b2[4] = {B0.x, B0.y, B1.x, B1.y};
            #pragma unroll
            for (int r = 0; r < 8; r++)
                #pragma unroll
                for (int c = 0; c < 4; c++)
                    fma2(acc[r][c], a2[r], b2[c]);
        }
    }

    float* Gp = d_G + (size_t)p * TT * DD + d0;
    #pragma unroll
    for (int r = 0; r < 8; r++)
        #pragma unroll
        for (int c = 0; c < 4; c++) {
            float lo, hi;
            unpack2(acc[r][c], lo, hi);
            atomicAdd(&Gp[(size_t)(ty * 8 + r) * DD + tx * 8 + c * 2],     lo);
            atomicAdd(&Gp[(size_t)(ty * 8 + r) * DD + tx * 8 + c * 2 + 1], hi);
        }
}

// ---------------- kernel 5: per-pair score S[p] ----------------
__global__ void __launch_bounds__(256) k_score(const float* __restrict__ text) {
    const int p = blockIdx.x, i = p >> 3, j = p & 7;
    __shared__ float sbeta[TT * MM];
    __shared__ float sls[MM];
    __shared__ float sdiag[TT];
    __shared__ float snrm[MM], sdot[MM];
    __shared__ float Es[TT * 128];
    const int tid = threadIdx.x, lane = tid & 31, warp = tid >> 5;
    const float* E = text + (size_t)j * TT * DD;

    for (int idx = tid; idx < TT * MM; idx += 256)
        sbeta[idx] = d_sExp[(size_t)p * TT * MM + idx];
    if (tid < MM) { snrm[tid] = 0.f; sdot[tid] = 0.f; }
    __syncthreads();
    if (tid < MM) {
        float s = 0.f;
        for (int t = 0; t < TT; t++) s += sbeta[t * MM + tid];
        sls[tid] = 1.0f / s;
    }
    __syncthreads();
    for (int idx = tid; idx < TT * MM; idx += 256) {
        float v = sbeta[idx] * sls[idx % MM];
        sbeta[idx] = v;
        if (i == j) d_betas[(size_t)i * TT * MM + idx] = v;
    }
    __syncthreads();

    for (int t = warp; t < TT; t += 8) {
        const float* Gr = d_G + ((size_t)p * TT + t) * DD;
        const float* Er = E + (size_t)t * DD;
        float s = 0.f;
        for (int d = lane; d < DD; d += 32) s = fmaf(Gr[d], Er[d], s);
        #pragma unroll
        for (int off = 16; off; off >>= 1) s += __shfl_down_sync(0xffffffffu, s, off);
        if (lane == 0) sdiag[t] = s / d_Zt[p * TT + t];
    }

    const float* U = d_u + (size_t)i * MM * DD;
    const int grp = tid >> 7;
    const int dl = tid & 127;
    for (int d0 = 0; d0 < DD; d0 += 128) {
        __syncthreads();
        for (int idx = tid; idx < TT * 128; idx += 256) {
            int t = idx >> 7, dloc = idx & 127;
            Es[idx] = E[(size_t)t * DD + d0 + dloc];
        }
        __syncthreads();
        for (int m = grp; m < MM; m += 2) {
            float v = 0.f;
            #pragma unroll 16
            for (int t = 0; t < TT; t++)
                v = fmaf(sbeta[t * MM + m], Es[t * 128 + dl], v);
            float nr = v * v;
            float dt = v * U[(size_t)m * DD + d0 + dl];
            #pragma unroll
            for (int off = 16; off; off >>= 1) {
                nr += __shfl_down_sync(0xffffffffu, nr, off);
                dt += __shfl_down_sync(0xffffffffu, dt, off);
            }
            if (lane == 0) { atomicAdd(&snrm[m], nr); atomicAdd(&sdot[m], dt); }
        }
    }
    __syncthreads();
    if (tid == 0) {
        float se = 0.f;
        for (int t = 0; t < TT; t++) se += expf(G2 * sdiag[t]);
        float r_qd = (1.0f / G2) * logf(se);
        float sm = 0.f;
        for (int m = 0; m < MM; m++)
            sm += expf(sdot[m] / ((float)HWW * sqrtf(snrm[m])));
        d_S[p] = r_qd + (1.0f / G2) * logf(sm);
    }
}

// ---------------- kernel 6: final scalar ----------------
__global__ void __launch_bounds__(256) k_final(const int* __restrict__ spinds,
                                               float* __restrict__ out) {
    __shared__ float sb[TT * MM];
    __shared__ float red[8];
    __shared__ float regsum;
    const int tid = threadIdx.x, lane = tid & 31, warp = tid >> 5;
    if (tid == 0) regsum = 0.f;
    for (int b = 0; b < BB; b++) {
        __syncthreads();
        for (int idx = tid; idx < TT * MM; idx += 256)
            sb[idx] = d_betas[(size_t)b * TT * MM + idx];
        __syncthreads();
        float lsum = 0.f;
        for (int idx = tid; idx < MM * MM; idx += 256) {
            int a = idx / MM, c = idx % MM;
            float v = 0.f;
            for (int t = 0; t < TT; t++)
                v = fmaf(sb[t * MM + a], sb[t * MM + c], v);
            lsum = fmaf(v, v, lsum);
        }
        for (int t = tid; t < TT; t += 256) {
            float v = 0.f;
            for (int m = 0; m < MM; m++)
                v = fmaf(sb[t * MM + m], sb[t * MM + m], v);
            lsum -= v * v;
        }
        #pragma unroll
        for (int off = 16; off; off >>= 1)
            lsum += __shfl_down_sync(0xffffffffu, lsum, off);
        if (lane == 0) red[warp] = lsum;
        __syncthreads();
        if (tid == 0) {
            float s = 0.f;
            for (int w = 0; w < 8; w++) s += red[w];
            regsum += sqrtf(fmaxf(s, 0.f));
        }
    }
    __syncthreads();
    if (tid == 0) {
        float l1 = 0.f, l2 = 0.f;
        for (int a = 0; a < BB; a++) {
            float num = expf(d_S[a * BB + a]);
            float pdq = 0.f, pqd = 0.f;
            for (int k = 0; k < 5; k++) {
                int sp = spinds[a * 5 + k];
                pdq += expf(d_S[a * BB + sp]);
                pqd += expf(d_S[sp * BB + a]);
            }
            l1 += num / pdq;
            l2 += num / pqd;
        }
        out[0] = -(l1 / BB) - (l2 / BB) + regsum / (float)(BB * TT * MM);
    }
}

// ---------------- launcher ----------------
extern "C" void kernel_launch(void* const* d_in, const int* in_sizes, int n_in,
                              void* d_out, int out_size) {
    const float* image  = (const float*)d_in[0];
    const float* text   = (const float*)d_in[1];
    const int*   spinds = (const int*)d_in[3];
    float* out = (float*)d_out;

    k_init<<<8192, 256>>>();
    {
        dim3 g(16, MM, BB);
        k_transpose<<<g, 256>>>(image);
    }
    {
        dim3 g(MM, BB);
        k_u<<<g, 256>>>();
    }
    {
        dim3 g((NN + 255) / 256, PP);   // 28 x 64
        k_sim<<<g, 256>>>(text);
    }
    {
        dim3 g(DD / 256, KSPLIT, PP);   // 2 x 4 x 64
        k_gmm<<<g, 256>>>();
    }
    k_score<<<PP, 256>>>(text);
    k_final<<<1, 256>>>(spinds, out);
}